// round 1
// baseline (speedup 1.0000x reference)
#include <cuda_runtime.h>

namespace {
constexpr int TOKENS = 16384;   // 4 * 4096
constexpr int D      = 2048;
constexpr int E      = 64;
constexpr int TM     = 64;      // tokens per block
constexpr int KC     = 64;      // K tile

constexpr size_t OFF_DISPATCH = 0;
constexpr size_t OFF_PROBS    = (size_t)TOKENS * E;            // 1048576
constexpr size_t OFF_TKP      = OFF_PROBS + (size_t)TOKENS * E; // 2097152
constexpr size_t OFF_TKI      = OFF_TKP + (size_t)TOKENS * 2;   // 2129920
}

__global__ __launch_bounds__(256) void moe_router_kernel(
    const float* __restrict__ x, const float* __restrict__ W, float* __restrict__ out)
{
    // xs: [TM][KC] = 4096 floats, ws: [KC][E] = 4096 floats.
    // After the mainloop the front of smem is reused for logits [64][65] = 4160 floats.
    __shared__ float smem[TM * KC + KC * E];
    float* xs = smem;
    float* ws = smem + TM * KC;

    const int tid = threadIdx.x;
    const int tx  = tid & 15;   // expert group: experts [tx*4, tx*4+3]
    const int ty  = tid >> 4;   // token group:  tokens  [ty*4, ty*4+3]
    const int tokBase = blockIdx.x * TM;

    // 4 tokens x 4 experts as packed f32x2 pairs: acc[token][pair]
    unsigned long long acc[4][2];
    #pragma unroll
    for (int i = 0; i < 4; i++) { acc[i][0] = 0ULL; acc[i][1] = 0ULL; }

    for (int k0 = 0; k0 < D; k0 += KC) {
        // cooperative tile loads: 1024 float4 each, 4 per thread, coalesced
        #pragma unroll
        for (int i = 0; i < 4; i++) {
            int f4  = tid + i * 256;           // 0..1023
            int row = f4 >> 4;                 // 0..63
            int col = (f4 & 15) << 2;          // 0..60
            *(float4*)&xs[row * KC + col] =
                *(const float4*)&x[(size_t)(tokBase + row) * D + k0 + col];
            // W tile is fully contiguous in global (row stride == E)
            *(float4*)&ws[f4 << 2] = *(const float4*)&W[(size_t)k0 * E + (f4 << 2)];
        }
        __syncthreads();

        #pragma unroll 8
        for (int kk = 0; kk < KC; kk++) {
            // 4 experts' weights: one LDS.128 (conflict-free per quarter-warp phase)
            ulonglong2 wd = *(const ulonglong2*)&ws[kk * E + (tx << 2)];
            #pragma unroll
            for (int i = 0; i < 4; i++) {
                float xv = xs[(ty * 4 + i) * KC + kk];   // warp-broadcast
                unsigned long long xd;
                asm("mov.b64 %0, {%1, %1};" : "=l"(xd) : "f"(xv));
                asm("fma.rn.f32x2 %0, %1, %2, %0;" : "+l"(acc[i][0]) : "l"(xd), "l"(wd.x));
                asm("fma.rn.f32x2 %0, %1, %2, %0;" : "+l"(acc[i][1]) : "l"(xd), "l"(wd.y));
            }
        }
        __syncthreads();
    }

    // scatter logits into smem [64][65] (pad avoids column bank conflicts in epilogue)
    #pragma unroll
    for (int i = 0; i < 4; i++) {
        #pragma unroll
        for (int j = 0; j < 2; j++) {
            float lo, hi;
            asm("mov.b64 {%0, %1}, %2;" : "=f"(lo), "=f"(hi) : "l"(acc[i][j]));
            int e = (tx << 2) + j * 2;
            smem[(ty * 4 + i) * 65 + e]     = lo;
            smem[(ty * 4 + i) * 65 + e + 1] = hi;
        }
    }
    __syncthreads();

    // one thread per token: softmax + top-2 + all four outputs
    if (tid < TM) {
        const int token = tokBase + tid;
        float* lrow = &smem[tid * 65];

        // top-2 on logits (== top-2 on probs; exp is monotone).
        // Strict '>' comparisons: ties keep the LOWER index, matching lax.top_k.
        float m1 = -1e30f, m2 = -1e30f;
        int   i1 = 0,      i2 = 0;
        #pragma unroll
        for (int e = 0; e < E; e++) {
            float l = lrow[e];
            if (l > m1)      { m2 = m1; i2 = i1; m1 = l; i1 = e; }
            else if (l > m2) { m2 = l;  i2 = e; }
        }

        float sum = 0.f;
        #pragma unroll
        for (int e = 0; e < E; e++) {
            float ev = expf(lrow[e] - m1);
            lrow[e] = ev;
            sum += ev;
        }
        float inv = 1.0f / sum;

        float4* prow = (float4*)&out[OFF_PROBS    + (size_t)token * E];
        float4* drow = (float4*)&out[OFF_DISPATCH + (size_t)token * E];
        #pragma unroll
        for (int g = 0; g < 16; g++) {
            float4 pv;
            pv.x = lrow[g * 4 + 0] * inv;
            pv.y = lrow[g * 4 + 1] * inv;
            pv.z = lrow[g * 4 + 2] * inv;
            pv.w = lrow[g * 4 + 3] * inv;
            prow[g] = pv;

            float dv[4] = {0.f, 0.f, 0.f, 0.f};
            if ((i1 >> 2) == g) dv[i1 & 3] = 1.0f;
            if ((i2 >> 2) == g) dv[i2 & 3] = 1.0f;
            drow[g] = make_float4(dv[0], dv[1], dv[2], dv[3]);
        }

        out[OFF_TKP + (size_t)token * 2 + 0] = lrow[i1] * inv;
        out[OFF_TKP + (size_t)token * 2 + 1] = lrow[i2] * inv;
        out[OFF_TKI + (size_t)token * 2 + 0] = (float)i1;
        out[OFF_TKI + (size_t)token * 2 + 1] = (float)i2;
    }
}

extern "C" void kernel_launch(void* const* d_in, const int* in_sizes, int n_in,
                              void* d_out, int out_size) {
    const float* x = (const float*)d_in[0];
    const float* W = (const float*)d_in[1];
    float* out = (float*)d_out;
    moe_router_kernel<<<TOKENS / TM, 256>>>(x, W, out);
}

// round 5
// speedup vs baseline: 1.5859x; 1.5859x over previous
#include <cuda_runtime.h>
#include <cstdint>

// ---------------------------------------------------------------------------
// MoE router: 3xTF32 mma.sync GEMM (16384x64x2048) + fused softmax/top-2.
// sm_80-compatible PTX only (mma.sync + cp.async; no "a"-suffix features).
// Precision: x = hi + lo (hi = fp32 masked to tf32 bits, lo exact residual).
//   hi*hi pass  -> per-32K-slab accumulator (exact products), Kahan-folded
//                  into running total (error ~3e-7 relative).
//   cross passes-> separate small-magnitude accumulator, added once at end.
// ---------------------------------------------------------------------------

namespace {
constexpr int TOKENS = 16384;
constexpr int DK     = 2048;
constexpr int E      = 64;
constexpr int TM     = 128;        // tokens per CTA
constexpr int KC     = 32;         // K per pipeline stage (= Kahan slab)
constexpr int NTILES = DK / KC;    // 64
constexpr int NT     = 256;        // threads

constexpr size_t OFF_PROBS = (size_t)TOKENS * E;
constexpr size_t OFF_TKP   = OFF_PROBS + (size_t)TOKENS * E;
constexpr size_t OFF_TKI   = OFF_TKP + (size_t)TOKENS * 2;

constexpr int A_STAGE = 16384;     // 128x32 f32
constexpr int B_BASE  = 32768;
constexpr int B_STAGE = 8192;      // 32x64 f32
}

__device__ __forceinline__ uint32_t smem_u32(const void* p) {
    uint32_t a;
    asm("{ .reg .u64 t; cvta.to.shared.u64 t, %1; cvt.u32.u64 %0, t; }" : "=r"(a) : "l"(p));
    return a;
}
__device__ __forceinline__ void cp16(uint32_t s, const void* g) {
    asm volatile("cp.async.cg.shared.global [%0], [%1], 16;" :: "r"(s), "l"(g));
}
#define CP_COMMIT() asm volatile("cp.async.commit_group;" ::: "memory")
#define CP_WAIT1()  asm volatile("cp.async.wait_group 1;" ::: "memory")
#define CP_WAIT0()  asm volatile("cp.async.wait_group 0;" ::: "memory")

#define MMA8(c, a, b)                                                          \
    asm volatile(                                                              \
        "mma.sync.aligned.m16n8k8.row.col.f32.tf32.tf32.f32 "                  \
        "{%0,%1,%2,%3}, {%4,%5,%6,%7}, {%8,%9}, {%0,%1,%2,%3};"                \
        : "+f"((c)[0]), "+f"((c)[1]), "+f"((c)[2]), "+f"((c)[3])               \
        : "r"((a)[0]), "r"((a)[1]), "r"((a)[2]), "r"((a)[3]),                  \
          "r"((b)[0]), "r"((b)[1]))

__global__ __launch_bounds__(NT, 1) void moe_router_mma(
    const float* __restrict__ x, const float* __restrict__ W, float* __restrict__ out)
{
    __shared__ __align__(16) char smem[49152];
    const uint32_t sbase = smem_u32(smem);

    const int tid  = threadIdx.x;
    const int wid  = tid >> 5;
    const int lane = tid & 31;
    const int wm   = wid >> 1;        // warp row: tokens [wm*32, +32)
    const int wn   = wid & 1;         // warp col: experts [wn*32, +32)
    const int g    = lane >> 2;
    const int tig  = lane & 3;
    const int tokBase = blockIdx.x * TM;

    float accT[2][4][4];   // hi-pass running total (Kahan sum)
    float accC[2][4][4];   // Kahan compensation
    float accL[2][4][4];   // cross-pass (lo) accumulator, small magnitude
    #pragma unroll
    for (int mt = 0; mt < 2; mt++)
        #pragma unroll
        for (int nt = 0; nt < 4; nt++)
            #pragma unroll
            for (int i = 0; i < 4; i++) {
                accT[mt][nt][i] = 0.f; accC[mt][nt][i] = 0.f; accL[mt][nt][i] = 0.f;
            }

    auto issue = [&](int t, int st) {
        const uint32_t Ab = sbase + st * A_STAGE;
        const uint32_t Bb = sbase + B_BASE + st * B_STAGE;
        const float* xt = x + (size_t)tokBase * DK + t * KC;
        #pragma unroll
        for (int j = 0; j < 4; j++) {
            int idx = tid + j * 256;
            int row = idx >> 3, ch = idx & 7;
            cp16(Ab + row * 128 + ((ch ^ (row & 7)) << 4),
                 xt + (size_t)row * DK + ch * 4);
        }
        const float* wt = W + (size_t)t * KC * E;
        #pragma unroll
        for (int j = 0; j < 2; j++) {
            int idx = tid + j * 256;
            int k = idx >> 4, ch = idx & 15;
            cp16(Bb + k * 256 + ((ch ^ (2 * (k & 3))) << 4),
                 wt + (size_t)k * E + ch * 4);
        }
    };

    issue(0, 0);
    CP_COMMIT();

    for (int t = 0; t < NTILES; t++) {
        const int st = t & 1;
        if (t + 1 < NTILES) {
            issue(t + 1, st ^ 1);
            CP_COMMIT();
            CP_WAIT1();
        } else {
            CP_WAIT0();
        }
        __syncthreads();

        const uint32_t Ab = sbase + st * A_STAGE;
        const uint32_t Bb = sbase + B_BASE + st * B_STAGE;

        // per-slab hi accumulator (exact tf32 products, 32 K-terms)
        float accS[2][4][4];
        #pragma unroll
        for (int mt = 0; mt < 2; mt++)
            #pragma unroll
            for (int nt = 0; nt < 4; nt++)
                #pragma unroll
                for (int i = 0; i < 4; i++) accS[mt][nt][i] = 0.f;

        #pragma unroll
        for (int ks = 0; ks < 4; ks++) {
            uint32_t ahi[2][4], alo[2][4];
            #pragma unroll
            for (int mt = 0; mt < 2; mt++) {
                #pragma unroll
                for (int i = 0; i < 4; i++) {
                    int row = wm * 32 + mt * 16 + g + (i & 1) * 8;
                    int ch  = (i >> 1) + 2 * ks;
                    uint32_t addr = Ab + row * 128 + ((ch ^ (row & 7)) << 4) + tig * 4;
                    uint32_t raw;
                    asm volatile("ld.shared.b32 %0, [%1];" : "=r"(raw) : "r"(addr));
                    uint32_t hb = raw & 0xffffe000u;
                    float lo = __uint_as_float(raw) - __uint_as_float(hb);
                    ahi[mt][i] = hb;
                    alo[mt][i] = __float_as_uint(lo);
                }
            }
            uint32_t bhi[4][2], blo[4][2];
            #pragma unroll
            for (int nt = 0; nt < 4; nt++) {
                #pragma unroll
                for (int ib = 0; ib < 2; ib++) {
                    int k = ks * 8 + ib * 4 + tig;
                    int n = wn * 32 + nt * 8 + g;
                    int ch = n >> 2;
                    uint32_t addr = Bb + k * 256 + ((ch ^ (2 * tig)) << 4) + (n & 3) * 4;
                    uint32_t raw;
                    asm volatile("ld.shared.b32 %0, [%1];" : "=r"(raw) : "r"(addr));
                    uint32_t hb = raw & 0xffffe000u;
                    float lo = __uint_as_float(raw) - __uint_as_float(hb);
                    bhi[nt][ib] = hb;
                    blo[nt][ib] = __float_as_uint(lo);
                }
            }
            #pragma unroll
            for (int mt = 0; mt < 2; mt++) {
                #pragma unroll
                for (int nt = 0; nt < 4; nt++) {
                    MMA8(accS[mt][nt], ahi[mt], bhi[nt]);   // exact products -> slab acc
                    MMA8(accL[mt][nt], ahi[mt], blo[nt]);   // small-magnitude acc
                    MMA8(accL[mt][nt], alo[mt], bhi[nt]);
                }
            }
        }

        // Kahan-fold slab into total (__fadd_rn: not reassociable by compiler)
        #pragma unroll
        for (int mt = 0; mt < 2; mt++) {
            #pragma unroll
            for (int nt = 0; nt < 4; nt++) {
                #pragma unroll
                for (int i = 0; i < 4; i++) {
                    float y  = __fadd_rn(accS[mt][nt][i], -accC[mt][nt][i]);
                    float tn = __fadd_rn(accT[mt][nt][i], y);
                    accC[mt][nt][i] = __fadd_rn(__fadd_rn(tn, -accT[mt][nt][i]), -y);
                    accT[mt][nt][i] = tn;
                }
            }
        }
        __syncthreads();
    }

    // ---- epilogue: logits = (T - C) + L -> smem [128][66] ----
    float* L = (float*)smem;
    #pragma unroll
    for (int mt = 0; mt < 2; mt++) {
        #pragma unroll
        for (int nt = 0; nt < 4; nt++) {
            int row0 = wm * 32 + mt * 16 + g;
            int col  = wn * 32 + nt * 8 + tig * 2;
            float v0 = __fadd_rn(__fadd_rn(accT[mt][nt][0], -accC[mt][nt][0]), accL[mt][nt][0]);
            float v1 = __fadd_rn(__fadd_rn(accT[mt][nt][1], -accC[mt][nt][1]), accL[mt][nt][1]);
            float v2 = __fadd_rn(__fadd_rn(accT[mt][nt][2], -accC[mt][nt][2]), accL[mt][nt][2]);
            float v3 = __fadd_rn(__fadd_rn(accT[mt][nt][3], -accC[mt][nt][3]), accL[mt][nt][3]);
            *(float2*)&L[row0 * 66 + col]       = make_float2(v0, v1);
            *(float2*)&L[(row0 + 8) * 66 + col] = make_float2(v2, v3);
        }
    }
    __syncthreads();

    if (tid < TM) {
        const int token = tokBase + tid;
        float* lrow = &L[tid * 66];

        float l[64];
        #pragma unroll
        for (int e = 0; e < 64; e++) l[e] = lrow[e];

        float m1 = -1e30f, m2 = -1e30f;
        int   i1 = 0,      i2 = 0;
        #pragma unroll
        for (int e = 0; e < 64; e++) {
            float v = l[e];
            if (v > m1)      { m2 = m1; i2 = i1; m1 = v; i1 = e; }
            else if (v > m2) { m2 = v;  i2 = e; }
        }

        float sum = 0.f;
        #pragma unroll
        for (int e = 0; e < 64; e++) { l[e] = expf(l[e] - m1); sum += l[e]; }
        const float inv = 1.0f / sum;

        float4* prow = (float4*)&out[OFF_PROBS + (size_t)token * 64];
        float4* drow = (float4*)&out[(size_t)token * 64];
        #pragma unroll
        for (int gq = 0; gq < 16; gq++) {
            float4 pv;
            pv.x = l[gq*4+0] * inv; pv.y = l[gq*4+1] * inv;
            pv.z = l[gq*4+2] * inv; pv.w = l[gq*4+3] * inv;
            prow[gq] = pv;
            float d0 = 0.f, d1 = 0.f, d2 = 0.f, d3 = 0.f;
            if ((i1 >> 2) == gq) { int r = i1 & 3; if (r==0) d0=1.f; else if (r==1) d1=1.f; else if (r==2) d2=1.f; else d3=1.f; }
            if ((i2 >> 2) == gq) { int r = i2 & 3; if (r==0) d0+=1.f; else if (r==1) d1+=1.f; else if (r==2) d2+=1.f; else d3+=1.f; }
            drow[gq] = make_float4(d0, d1, d2, d3);
        }
        out[OFF_TKP + (size_t)token * 2 + 0] = l[i1] * inv;
        out[OFF_TKP + (size_t)token * 2 + 1] = l[i2] * inv;
        out[OFF_TKI + (size_t)token * 2 + 0] = (float)i1;
        out[OFF_TKI + (size_t)token * 2 + 1] = (float)i2;
    }
}

extern "C" void kernel_launch(void* const* d_in, const int* in_sizes, int n_in,
                              void* d_out, int out_size) {
    const float* x = (const float*)d_in[0];
    const float* W = (const float*)d_in[1];
    float* out = (float*)d_out;
    moe_router_mma<<<TOKENS / TM, NT>>>(x, W, out);
}

// round 6
// speedup vs baseline: 1.7437x; 1.0995x over previous
#include <cuda_runtime.h>
#include <cstdint>

// ---------------------------------------------------------------------------
// MoE router: 3xTF32 mma.sync GEMM (16384x64x2048) + fused softmax/top-2.
// sm_80-compatible PTX only. R6: 2 CTAs/SM (grid 256, TM=64, 128 thr),
// plain slab-fold instead of Kahan (error ~5e-7, chain of 64 exact slabs).
// x = hi + lo; hi*hi -> per-slab acc (exact products) -> folded; cross
// passes -> separate small-magnitude accumulator added at the end.
// ---------------------------------------------------------------------------

namespace {
constexpr int TOKENS = 16384;
constexpr int DK     = 2048;
constexpr int E      = 64;
constexpr int TM     = 64;         // tokens per CTA
constexpr int KC     = 32;         // K per pipeline stage (= slab)
constexpr int NTILES = DK / KC;    // 64
constexpr int NT     = 128;        // threads per CTA (4 warps)

constexpr size_t OFF_PROBS = (size_t)TOKENS * E;
constexpr size_t OFF_TKP   = OFF_PROBS + (size_t)TOKENS * E;
constexpr size_t OFF_TKI   = OFF_TKP + (size_t)TOKENS * 2;

constexpr int A_STAGE = 8192;      // 64x32 f32
constexpr int B_BASE  = 16384;
constexpr int B_STAGE = 8192;      // 32x64 f32
}

__device__ __forceinline__ uint32_t smem_u32(const void* p) {
    uint32_t a;
    asm("{ .reg .u64 t; cvta.to.shared.u64 t, %1; cvt.u32.u64 %0, t; }" : "=r"(a) : "l"(p));
    return a;
}
__device__ __forceinline__ void cp16(uint32_t s, const void* g) {
    asm volatile("cp.async.cg.shared.global [%0], [%1], 16;" :: "r"(s), "l"(g));
}
#define CP_COMMIT() asm volatile("cp.async.commit_group;" ::: "memory")
#define CP_WAIT1()  asm volatile("cp.async.wait_group 1;" ::: "memory")
#define CP_WAIT0()  asm volatile("cp.async.wait_group 0;" ::: "memory")

#define MMA8(c, a, b)                                                          \
    asm volatile(                                                              \
        "mma.sync.aligned.m16n8k8.row.col.f32.tf32.tf32.f32 "                  \
        "{%0,%1,%2,%3}, {%4,%5,%6,%7}, {%8,%9}, {%0,%1,%2,%3};"                \
        : "+f"((c)[0]), "+f"((c)[1]), "+f"((c)[2]), "+f"((c)[3])               \
        : "r"((a)[0]), "r"((a)[1]), "r"((a)[2]), "r"((a)[3]),                  \
          "r"((b)[0]), "r"((b)[1]))

__global__ __launch_bounds__(NT, 2) void moe_router_mma(
    const float* __restrict__ x, const float* __restrict__ W, float* __restrict__ out)
{
    __shared__ __align__(16) char smem[32768];
    const uint32_t sbase = smem_u32(smem);

    const int tid  = threadIdx.x;
    const int wid  = tid >> 5;        // 0..3
    const int lane = tid & 31;
    const int wm   = wid >> 1;        // warp row: tokens [wm*32, +32)
    const int wn   = wid & 1;         // warp col: experts [wn*32, +32)
    const int g    = lane >> 2;
    const int tig  = lane & 3;
    const int tokBase = blockIdx.x * TM;

    float accT[2][4][4];   // hi-pass running total (chain of exact slabs)
    float accL[2][4][4];   // cross-pass (lo) accumulator, small magnitude
    #pragma unroll
    for (int mt = 0; mt < 2; mt++)
        #pragma unroll
        for (int nt = 0; nt < 4; nt++)
            #pragma unroll
            for (int i = 0; i < 4; i++) { accT[mt][nt][i] = 0.f; accL[mt][nt][i] = 0.f; }

    // A[row 0..63][chunk 0..7 of 4 floats], phys chunk = chunk ^ (row&7)
    // B[k 0..31][chunk 0..15 of 4 floats],  phys chunk = chunk ^ (2*(k&3))
    auto issue = [&](int t, int st) {
        const uint32_t Ab = sbase + st * A_STAGE;
        const uint32_t Bb = sbase + B_BASE + st * B_STAGE;
        const float* xt = x + (size_t)tokBase * DK + t * KC;
        #pragma unroll
        for (int j = 0; j < 4; j++) {
            int idx = tid + j * NT;                 // 0..511
            int row = idx >> 3, ch = idx & 7;
            cp16(Ab + row * 128 + ((ch ^ (row & 7)) << 4),
                 xt + (size_t)row * DK + ch * 4);
        }
        const float* wt = W + (size_t)t * KC * E;
        #pragma unroll
        for (int j = 0; j < 4; j++) {
            int idx = tid + j * NT;                 // 0..511
            int k = idx >> 4, ch = idx & 15;
            cp16(Bb + k * 256 + ((ch ^ (2 * (k & 3))) << 4),
                 wt + (size_t)k * E + ch * 4);
        }
    };

    issue(0, 0);
    CP_COMMIT();

    for (int t = 0; t < NTILES; t++) {
        const int st = t & 1;
        if (t + 1 < NTILES) {
            issue(t + 1, st ^ 1);
            CP_COMMIT();
            CP_WAIT1();
        } else {
            CP_WAIT0();
        }
        __syncthreads();

        const uint32_t Ab = sbase + st * A_STAGE;
        const uint32_t Bb = sbase + B_BASE + st * B_STAGE;

        // per-slab hi accumulator (exact tf32 products, 32 K-terms)
        float accS[2][4][4];
        #pragma unroll
        for (int mt = 0; mt < 2; mt++)
            #pragma unroll
            for (int nt = 0; nt < 4; nt++)
                #pragma unroll
                for (int i = 0; i < 4; i++) accS[mt][nt][i] = 0.f;

        #pragma unroll
        for (int ks = 0; ks < 4; ks++) {
            uint32_t ahi[2][4], alo[2][4];
            #pragma unroll
            for (int mt = 0; mt < 2; mt++) {
                #pragma unroll
                for (int i = 0; i < 4; i++) {
                    int row = wm * 32 + mt * 16 + g + (i & 1) * 8;
                    int ch  = (i >> 1) + 2 * ks;
                    uint32_t addr = Ab + row * 128 + ((ch ^ (row & 7)) << 4) + tig * 4;
                    uint32_t raw;
                    asm volatile("ld.shared.b32 %0, [%1];" : "=r"(raw) : "r"(addr));
                    uint32_t hb = raw & 0xffffe000u;
                    float lo = __uint_as_float(raw) - __uint_as_float(hb);
                    ahi[mt][i] = hb;
                    alo[mt][i] = __float_as_uint(lo);
                }
            }
            uint32_t bhi[4][2], blo[4][2];
            #pragma unroll
            for (int nt = 0; nt < 4; nt++) {
                #pragma unroll
                for (int ib = 0; ib < 2; ib++) {
                    int k = ks * 8 + ib * 4 + tig;
                    int n = wn * 32 + nt * 8 + g;
                    int ch = n >> 2;
                    uint32_t addr = Bb + k * 256 + ((ch ^ (2 * tig)) << 4) + (n & 3) * 4;
                    uint32_t raw;
                    asm volatile("ld.shared.b32 %0, [%1];" : "=r"(raw) : "r"(addr));
                    uint32_t hb = raw & 0xffffe000u;
                    float lo = __uint_as_float(raw) - __uint_as_float(hb);
                    bhi[nt][ib] = hb;
                    blo[nt][ib] = __float_as_uint(lo);
                }
            }
            #pragma unroll
            for (int mt = 0; mt < 2; mt++) {
                #pragma unroll
                for (int nt = 0; nt < 4; nt++) {
                    MMA8(accS[mt][nt], ahi[mt], bhi[nt]);   // exact -> slab acc
                    MMA8(accL[mt][nt], ahi[mt], blo[nt]);   // small-magnitude acc
                    MMA8(accL[mt][nt], alo[mt], bhi[nt]);
                }
            }
        }

        // fold slab into running total (one rn-add per accumulator)
        #pragma unroll
        for (int mt = 0; mt < 2; mt++)
            #pragma unroll
            for (int nt = 0; nt < 4; nt++)
                #pragma unroll
                for (int i = 0; i < 4; i++)
                    accT[mt][nt][i] = __fadd_rn(accT[mt][nt][i], accS[mt][nt][i]);
        __syncthreads();
    }

    // ---- epilogue: logits = T + L -> smem [64][66] ----
    float* L = (float*)smem;
    #pragma unroll
    for (int mt = 0; mt < 2; mt++) {
        #pragma unroll
        for (int nt = 0; nt < 4; nt++) {
            int row0 = wm * 32 + mt * 16 + g;
            int col  = wn * 32 + nt * 8 + tig * 2;
            float v0 = __fadd_rn(accT[mt][nt][0], accL[mt][nt][0]);
            float v1 = __fadd_rn(accT[mt][nt][1], accL[mt][nt][1]);
            float v2 = __fadd_rn(accT[mt][nt][2], accL[mt][nt][2]);
            float v3 = __fadd_rn(accT[mt][nt][3], accL[mt][nt][3]);
            *(float2*)&L[row0 * 66 + col]       = make_float2(v0, v1);
            *(float2*)&L[(row0 + 8) * 66 + col] = make_float2(v2, v3);
        }
    }
    __syncthreads();

    if (tid < TM) {
        const int token = tokBase + tid;
        float* lrow = &L[tid * 66];

        float l[64];
        #pragma unroll
        for (int e = 0; e < 64; e++) l[e] = lrow[e];

        // top-2; strict '>' keeps lower index on ties (matches lax.top_k)
        float m1 = -1e30f, m2 = -1e30f;
        int   i1 = 0,      i2 = 0;
        #pragma unroll
        for (int e = 0; e < 64; e++) {
            float v = l[e];
            if (v > m1)      { m2 = m1; i2 = i1; m1 = v; i1 = e; }
            else if (v > m2) { m2 = v;  i2 = e; }
        }

        float sum = 0.f;
        #pragma unroll
        for (int e = 0; e < 64; e++) { l[e] = expf(l[e] - m1); sum += l[e]; }
        const float inv = 1.0f / sum;

        float4* prow = (float4*)&out[OFF_PROBS + (size_t)token * 64];
        float4* drow = (float4*)&out[(size_t)token * 64];
        #pragma unroll
        for (int gq = 0; gq < 16; gq++) {
            float4 pv;
            pv.x = l[gq*4+0] * inv; pv.y = l[gq*4+1] * inv;
            pv.z = l[gq*4+2] * inv; pv.w = l[gq*4+3] * inv;
            prow[gq] = pv;
            float d0 = 0.f, d1 = 0.f, d2 = 0.f, d3 = 0.f;
            if ((i1 >> 2) == gq) { int r = i1 & 3; if (r==0) d0=1.f; else if (r==1) d1=1.f; else if (r==2) d2=1.f; else d3=1.f; }
            if ((i2 >> 2) == gq) { int r = i2 & 3; if (r==0) d0+=1.f; else if (r==1) d1+=1.f; else if (r==2) d2+=1.f; else d3+=1.f; }
            drow[gq] = make_float4(d0, d1, d2, d3);
        }
        out[OFF_TKP + (size_t)token * 2 + 0] = l[i1] * inv;
        out[OFF_TKP + (size_t)token * 2 + 1] = l[i2] * inv;
        out[OFF_TKI + (size_t)token * 2 + 0] = (float)i1;
        out[OFF_TKI + (size_t)token * 2 + 1] = (float)i2;
    }
}

extern "C" void kernel_launch(void* const* d_in, const int* in_sizes, int n_in,
                              void* d_out, int out_size) {
    const float* x = (const float*)d_in[0];
    const float* W = (const float*)d_in[1];
    float* out = (float*)d_out;
    moe_router_mma<<<TOKENS / TM, NT>>>(x, W, out);
}